// round 1
// baseline (speedup 1.0000x reference)
#include <cuda_runtime.h>
#include <math.h>

// Problem constants
static constexpr int kB = 8;
static constexpr int kS = 2048;
static constexpr int kD = 256;
static constexpr int kM = kB * kS;          // 16384 rows for projections
static constexpr int N_QCHUNK = 16;         // colsum split over queries
static constexpr int N_KCHUNK = 32;         // out split over keys

// Scratch (static device memory — no allocations allowed)
__device__ float g_Q[kB * kS * kD];                         // 16 MB
__device__ float g_K[kB * kS * kD];                         // 16 MB
__device__ float g_V[kB * kS * kD];                         // 16 MB
__device__ float g_P[(size_t)kB * kS * kS];                 // 134 MB (scores -> probs)
__device__ float g_w[kB * kS];                              // column sums of attn
__device__ float g_wpart[N_QCHUNK * kB * kS];               // colsum partials
__device__ float g_opart[N_KCHUNK * kB * kD];               // output partials

// ---------------------------------------------------------------------------
// Generic TN GEMM: C[m,n] = sum_k A[m,k] * Bm[n,k]  (+bias or scale+mask)
// Tile 128x128, BK=16, 256 threads, 8x8 micro-tile, k-major smem, float4 frags.
// mask != nullptr  -> scores mode: C = acc*scale, masked cols set to -inf
// mask == nullptr  -> projection mode: C = acc + bias[n]
// ---------------------------------------------------------------------------
__global__ __launch_bounds__(256)
void gemm_tn_kernel(const float* __restrict__ A,
                    const float* __restrict__ Bm,
                    const float* __restrict__ bias,
                    const int*   __restrict__ mask,
                    float* __restrict__ C,
                    int M, int N, int K,
                    long long strideA, long long strideB, long long strideC,
                    int maskStride, float scale)
{
    constexpr int BM = 128, BN = 128, BK = 16, TM = 8, TN = 8;
    __shared__ float As[BK][BM];
    __shared__ float Bs[BK][BN];

    const int b = blockIdx.z;
    A  += (size_t)b * strideA;
    Bm += (size_t)b * strideB;
    C  += (size_t)b * strideC;
    if (mask) mask += (size_t)b * maskStride;

    const int tid = threadIdx.x;
    const int tx = tid & 15;
    const int ty = tid >> 4;
    const int bm = blockIdx.y * BM;
    const int bn = blockIdx.x * BN;

    float acc[TM][TN];
#pragma unroll
    for (int i = 0; i < TM; i++)
#pragma unroll
        for (int j = 0; j < TN; j++) acc[i][j] = 0.0f;

    for (int k0 = 0; k0 < K; k0 += BK) {
        // Load A tile (128x16) and B tile (128x16), transposed to k-major smem.
        // 2048 floats each = 512 float4 = 256 threads x 2.
#pragma unroll
        for (int i = 0; i < 2; i++) {
            int li  = tid + i * 256;        // 0..511
            int row = li >> 2;              // 0..127
            int kc  = (li & 3) << 2;        // 0,4,8,12
            float4 va = *(const float4*)(A  + (size_t)(bm + row) * K + k0 + kc);
            As[kc + 0][row] = va.x; As[kc + 1][row] = va.y;
            As[kc + 2][row] = va.z; As[kc + 3][row] = va.w;
            float4 vb = *(const float4*)(Bm + (size_t)(bn + row) * K + k0 + kc);
            Bs[kc + 0][row] = vb.x; Bs[kc + 1][row] = vb.y;
            Bs[kc + 2][row] = vb.z; Bs[kc + 3][row] = vb.w;
        }
        __syncthreads();

#pragma unroll
        for (int kk = 0; kk < BK; kk++) {
            float a[TM], bb[TN];
            *(float4*)&a[0]  = *(const float4*)&As[kk][ty * TM];
            *(float4*)&a[4]  = *(const float4*)&As[kk][ty * TM + 4];
            *(float4*)&bb[0] = *(const float4*)&Bs[kk][tx * TN];
            *(float4*)&bb[4] = *(const float4*)&Bs[kk][tx * TN + 4];
#pragma unroll
            for (int i = 0; i < TM; i++)
#pragma unroll
                for (int j = 0; j < TN; j++)
                    acc[i][j] = fmaf(a[i], bb[j], acc[i][j]);
        }
        __syncthreads();
    }

    const int row0 = bm + ty * TM;
    const int col0 = bn + tx * TN;
    const float NEG_INF = __int_as_float(0xff800000u);

    if (mask) {
        int mk[TN];
#pragma unroll
        for (int j = 0; j < TN; j++) mk[j] = mask[col0 + j];
#pragma unroll
        for (int i = 0; i < TM; i++) {
            float o[TN];
#pragma unroll
            for (int j = 0; j < TN; j++) {
                o[j] = acc[i][j] * scale;
                if (mk[j] == 0) o[j] = NEG_INF;
            }
            *(float4*)&C[(size_t)(row0 + i) * N + col0]     = make_float4(o[0], o[1], o[2], o[3]);
            *(float4*)&C[(size_t)(row0 + i) * N + col0 + 4] = make_float4(o[4], o[5], o[6], o[7]);
        }
    } else {
        float bb[TN];
#pragma unroll
        for (int j = 0; j < TN; j++) bb[j] = bias[col0 + j];
#pragma unroll
        for (int i = 0; i < TM; i++) {
            float o[TN];
#pragma unroll
            for (int j = 0; j < TN; j++) o[j] = acc[i][j] + bb[j];
            *(float4*)&C[(size_t)(row0 + i) * N + col0]     = make_float4(o[0], o[1], o[2], o[3]);
            *(float4*)&C[(size_t)(row0 + i) * N + col0 + 4] = make_float4(o[4], o[5], o[6], o[7]);
        }
    }
}

// ---------------------------------------------------------------------------
// Row softmax in place: one block per (b,q) row of 2048 elements.
// ---------------------------------------------------------------------------
__device__ __forceinline__ float block_reduce_max(float v)
{
    __shared__ float sm[8];
    for (int o = 16; o; o >>= 1) v = fmaxf(v, __shfl_xor_sync(0xffffffffu, v, o));
    if ((threadIdx.x & 31) == 0) sm[threadIdx.x >> 5] = v;
    __syncthreads();
    if (threadIdx.x < 32) {
        v = sm[threadIdx.x & 7];
        for (int o = 4; o; o >>= 1) v = fmaxf(v, __shfl_xor_sync(0xffffffffu, v, o));
        if (threadIdx.x == 0) sm[0] = v;
    }
    __syncthreads();
    float r = sm[0];
    __syncthreads();
    return r;
}

__device__ __forceinline__ float block_reduce_sum(float v)
{
    __shared__ float sm[8];
    for (int o = 16; o; o >>= 1) v += __shfl_xor_sync(0xffffffffu, v, o);
    if ((threadIdx.x & 31) == 0) sm[threadIdx.x >> 5] = v;
    __syncthreads();
    if (threadIdx.x < 32) {
        v = sm[threadIdx.x & 7];
        for (int o = 4; o; o >>= 1) v += __shfl_xor_sync(0xffffffffu, v, o);
        if (threadIdx.x == 0) sm[0] = v;
    }
    __syncthreads();
    float r = sm[0];
    __syncthreads();
    return r;
}

__global__ __launch_bounds__(256)
void softmax_rows_kernel(float* __restrict__ P)
{
    float* p = P + (size_t)blockIdx.x * kS;
    const int tid = threadIdx.x;

    float x[8];
    *(float4*)&x[0] = *(const float4*)&p[tid * 8];
    *(float4*)&x[4] = *(const float4*)&p[tid * 8 + 4];

    float m = x[0];
#pragma unroll
    for (int i = 1; i < 8; i++) m = fmaxf(m, x[i]);
    m = block_reduce_max(m);

    float e[8];
    float s = 0.0f;
#pragma unroll
    for (int i = 0; i < 8; i++) {
        e[i] = expf(x[i] - m);   // exp(-inf - m) == 0 for masked keys
        s += e[i];
    }
    s = block_reduce_sum(s);
    const float inv = 1.0f / s;

#pragma unroll
    for (int i = 0; i < 8; i++) e[i] *= inv;
    *(float4*)&p[tid * 8]     = make_float4(e[0], e[1], e[2], e[3]);
    *(float4*)&p[tid * 8 + 4] = make_float4(e[4], e[5], e[6], e[7]);
}

// ---------------------------------------------------------------------------
// Column sums of attn:  w[b,k] = sum_q P[b,q,k], split over 16 query chunks.
// ---------------------------------------------------------------------------
__global__ __launch_bounds__(256)
void colsum_part_kernel(const float* __restrict__ P, float* __restrict__ wpart)
{
    const int kt    = blockIdx.x;   // 0..7   (key tile of 256)
    const int b     = blockIdx.y;   // 0..7
    const int chunk = blockIdx.z;   // 0..15  (128 query rows each)
    const int k = kt * 256 + threadIdx.x;

    const float* base = P + ((size_t)b * kS + (size_t)chunk * 128) * kS + k;
    float s = 0.0f;
#pragma unroll 8
    for (int q = 0; q < 128; q++) s += base[(size_t)q * kS];
    wpart[(size_t)chunk * (kB * kS) + b * kS + k] = s;
}

__global__ __launch_bounds__(256)
void colsum_reduce_kernel(const float* __restrict__ wpart, float* __restrict__ w)
{
    const int i = blockIdx.x * 256 + threadIdx.x;  // < kB*kS
    float s = 0.0f;
#pragma unroll
    for (int c = 0; c < N_QCHUNK; c++) s += wpart[(size_t)c * (kB * kS) + i];
    w[i] = s;
}

// ---------------------------------------------------------------------------
// out[b,d] = (1/S) * sum_k w[b,k] * V[b,k,d], split over 32 key chunks of 64.
// ---------------------------------------------------------------------------
__global__ __launch_bounds__(256)
void out_part_kernel(const float* __restrict__ w, const float* __restrict__ V,
                     float* __restrict__ opart)
{
    const int chunk = blockIdx.x;   // 0..31
    const int b     = blockIdx.y;   // 0..7
    const int d     = threadIdx.x;  // 0..255

    const float* vb = V + ((size_t)b * kS + (size_t)chunk * 64) * kD;
    const float* wb = w + b * kS + chunk * 64;
    float s = 0.0f;
#pragma unroll
    for (int k = 0; k < 64; k++) s = fmaf(wb[k], vb[(size_t)k * kD + d], s);
    opart[(size_t)(chunk * kB + b) * kD + d] = s;
}

__global__ __launch_bounds__(256)
void out_reduce_kernel(const float* __restrict__ opart, float* __restrict__ out)
{
    const int i = blockIdx.x * 256 + threadIdx.x;  // < kB*kD
    float s = 0.0f;
#pragma unroll
    for (int c = 0; c < N_KCHUNK; c++) s += opart[(size_t)c * (kB * kD) + i];
    out[i] = s * (1.0f / (float)kS);
}

// ---------------------------------------------------------------------------
// Launch
// ---------------------------------------------------------------------------
extern "C" void kernel_launch(void* const* d_in, const int* in_sizes, int n_in,
                              void* d_out, int out_size)
{
    const float* nodes = (const float*)d_in[0];
    const int*   mask  = (const int*)  d_in[1];
    const float* Wq    = (const float*)d_in[2];
    const float* bq    = (const float*)d_in[3];
    const float* Wk    = (const float*)d_in[4];
    const float* bk    = (const float*)d_in[5];
    const float* Wv    = (const float*)d_in[6];
    const float* bv    = (const float*)d_in[7];
    float* out = (float*)d_out;

    float *Q, *K, *V, *P, *w, *wpart, *opart;
    cudaGetSymbolAddress((void**)&Q,     g_Q);
    cudaGetSymbolAddress((void**)&K,     g_K);
    cudaGetSymbolAddress((void**)&V,     g_V);
    cudaGetSymbolAddress((void**)&P,     g_P);
    cudaGetSymbolAddress((void**)&w,     g_w);
    cudaGetSymbolAddress((void**)&wpart, g_wpart);
    cudaGetSymbolAddress((void**)&opart, g_opart);

    dim3 blk(256);

    // Projections: C[16384,256] = nodes @ W^T + b
    dim3 gproj(kD / 128, kM / 128, 1);
    gemm_tn_kernel<<<gproj, blk>>>(nodes, Wq, bq, nullptr, Q, kM, kD, kD, 0, 0, 0, 0, 1.0f);
    gemm_tn_kernel<<<gproj, blk>>>(nodes, Wk, bk, nullptr, K, kM, kD, kD, 0, 0, 0, 0, 1.0f);
    gemm_tn_kernel<<<gproj, blk>>>(nodes, Wv, bv, nullptr, V, kM, kD, kD, 0, 0, 0, 0, 1.0f);

    // Scores: P[b] = Q[b] @ K[b]^T / sqrt(D), masked keys -> -inf
    dim3 gsc(kS / 128, kS / 128, kB);
    gemm_tn_kernel<<<gsc, blk>>>(Q, K, nullptr, mask, P, kS, kS, kD,
                                 (long long)kS * kD, (long long)kS * kD,
                                 (long long)kS * kS, kS, 0.0625f);

    // Row softmax in place
    softmax_rows_kernel<<<kB * kS, blk>>>(P);

    // Column sums of attn (mean-over-q trick): w[b,k] = sum_q P[b,q,k]
    colsum_part_kernel<<<dim3(8, kB, N_QCHUNK), blk>>>(P, wpart);
    colsum_reduce_kernel<<<(kB * kS) / 256, blk>>>(wpart, w);

    // out[b,d] = (1/S) sum_k w[b,k] V[b,k,d]
    out_part_kernel<<<dim3(N_KCHUNK, kB), blk>>>(w, V, opart);
    out_reduce_kernel<<<(kB * kD) / 256, blk>>>(opart, out);
}

// round 3
// speedup vs baseline: 2.4274x; 2.4274x over previous
#include <cuda_runtime.h>
#include <cstdint>
#include <math.h>

// ---------------------------------------------------------------------------
// Problem constants
// ---------------------------------------------------------------------------
static constexpr int kB = 8;
static constexpr int kS = 2048;
static constexpr int kD = 256;
static constexpr int kM = kB * kS;
static constexpr int QCH = 64;       // softmax/colsum: 32 rows per chunk
static constexpr int N_KCHUNK = 32;  // output split over keys

// Scratch (static device memory)
__device__ float g_Q[kB * kS * kD];
__device__ float g_K[kB * kS * kD];
__device__ float g_V[kB * kS * kD];
__device__ float g_P[(size_t)kB * kS * kS];       // raw masked scores
__device__ float g_w[kB * kS];
__device__ float g_wpart[QCH * kB * kS];
__device__ float g_opart[N_KCHUNK * kB * kD];

// Shared memory layout for the GEMM kernel (sized for the tcgen05 path;
// the SIMT fallback reuses a prefix of it).
//   [0,8)      mbar
//   [8,12)     tmem ptr
//   [16,528)   mask[128]
//   [528,1040) bias[128]
//   [2048,...) 4 tiles of 128x32 f32 (A_hi, A_lo, B_hi, B_lo), 16 KB each
static constexpr int SMEM_AH = 2048;
static constexpr int SMEM_AL = SMEM_AH + 16384;
static constexpr int SMEM_BH = SMEM_AL + 16384;
static constexpr int SMEM_BL = SMEM_BH + 16384;
static constexpr int SMEM_TOTAL = SMEM_BL + 16384;   // 67584

#if defined(__CUDA_ARCH__) && defined(__CUDA_ARCH_FEAT_SM103_ALL)
#define HAS_TCGEN05 1
#else
#define HAS_TCGEN05 0
#endif

// ---------------------------------------------------------------------------
// PTX helpers — only compiled on the sm_103a pass
// ---------------------------------------------------------------------------
#if HAS_TCGEN05
__device__ __forceinline__ uint32_t elect_one_pred() {
    uint32_t pred;
    asm volatile(
        "{\n\t.reg .pred p;\n\t"
        "elect.sync _|p, 0xFFFFFFFF;\n\t"
        "selp.b32 %0, 1, 0, p;\n\t}"
        : "=r"(pred));
    return pred;
}

#define TCGEN05_ALLOC(smem_result_addr, nCols) \
    asm volatile("tcgen05.alloc.cta_group::1.sync.aligned.shared::cta.b32 [%0], %1;" \
                 :: "r"((uint32_t)(smem_result_addr)), "r"((uint32_t)(nCols)) : "memory")

#define TCGEN05_DEALLOC(tmem_addr, nCols) \
    asm volatile("tcgen05.dealloc.cta_group::1.sync.aligned.b32 %0, %1;" \
                 :: "r"(tmem_addr), "r"((uint32_t)(nCols)))

#define TCGEN05_RELINQUISH() \
    asm volatile("tcgen05.relinquish_alloc_permit.cta_group::1.sync.aligned;")

#define TCGEN05_COMMIT(mbar_smem_addr) \
    asm volatile("tcgen05.commit.cta_group::1.mbarrier::arrive::one.shared::cluster.b64 [%0];" \
                 :: "r"((uint32_t)(mbar_smem_addr)) : "memory")

#define TCGEN05_FENCE_AFTER() \
    asm volatile("tcgen05.fence::after_thread_sync;" ::: "memory")

#define TCGEN05_WAIT_LD() \
    asm volatile("tcgen05.wait::ld.sync.aligned;" ::: "memory")

#define MBARRIER_INIT(mbar_smem_addr, count) \
    asm volatile("mbarrier.init.shared.b64 [%0], %1;" \
                 :: "r"((uint32_t)(mbar_smem_addr)), "r"((uint32_t)(count)) : "memory")

#define MBARRIER_WAIT_PARITY(mbar_smem_addr, phase_parity) do { \
    uint32_t _mbar = (uint32_t)(mbar_smem_addr); \
    uint32_t _parity = (uint32_t)(phase_parity); \
    uint32_t _done; \
    asm volatile( \
        "{\n\t.reg .pred p;\n\t" \
        "mbarrier.try_wait.parity.acquire.cta.shared::cta.b64 p, [%1], %2;\n\t" \
        "selp.b32 %0, 1, 0, p;\n\t}" \
        : "=r"(_done) : "r"(_mbar), "r"(_parity) : "memory"); \
    if (!_done) { \
        asm volatile( \
            "{\n\t.reg .pred P1;\n\t" \
            "WAIT_LOOP_%=:\n\t" \
            "mbarrier.try_wait.parity.acquire.cta.shared::cta.b64 P1, [%0], %1, 0x989680;\n\t" \
            "@P1 bra.uni WAIT_DONE_%=;\n\t" \
            "bra.uni WAIT_LOOP_%=;\n\t" \
            "WAIT_DONE_%=:\n\t}" \
            :: "r"(_mbar), "r"(_parity) : "memory"); \
    } \
} while(0)

#define FENCE_PROXY_ASYNC_SHARED_CTA() \
    asm volatile("fence.proxy.async.shared::cta;" ::: "memory")

#define TCGEN05_LD_32X32B_X32(r, tmem_addr) \
    asm volatile( \
        "tcgen05.ld.sync.aligned.32x32b.x32.b32 " \
        "{%0, %1, %2, %3, %4, %5, %6, %7, " \
        " %8, %9, %10, %11, %12, %13, %14, %15, " \
        " %16, %17, %18, %19, %20, %21, %22, %23, " \
        " %24, %25, %26, %27, %28, %29, %30, %31}, [%32];" \
        : "=r"((r)[0]),  "=r"((r)[1]),  "=r"((r)[2]),  "=r"((r)[3]), \
          "=r"((r)[4]),  "=r"((r)[5]),  "=r"((r)[6]),  "=r"((r)[7]), \
          "=r"((r)[8]),  "=r"((r)[9]),  "=r"((r)[10]), "=r"((r)[11]), \
          "=r"((r)[12]), "=r"((r)[13]), "=r"((r)[14]), "=r"((r)[15]), \
          "=r"((r)[16]), "=r"((r)[17]), "=r"((r)[18]), "=r"((r)[19]), \
          "=r"((r)[20]), "=r"((r)[21]), "=r"((r)[22]), "=r"((r)[23]), \
          "=r"((r)[24]), "=r"((r)[25]), "=r"((r)[26]), "=r"((r)[27]), \
          "=r"((r)[28]), "=r"((r)[29]), "=r"((r)[30]), "=r"((r)[31]) \
        : "r"(tmem_addr))

// tf32 SS MMA (A in SMEM, B in SMEM, K=8 per instruction)
#define TCGEN05_MMA_TF32_SS(d_tmem, a_desc, b_desc, idesc, enable_d) do { \
    uint32_t _en = (enable_d) ? 1u : 0u; \
    uint32_t _zero = 0u; \
    asm volatile( \
        "{\n\t.reg .pred p;\n\t" \
        "setp.ne.u32 p, %5, 0;\n\t" \
        "tcgen05.mma.cta_group::1.kind::tf32 [%0], %1, %2, %3, {%4, %4, %4, %4}, p;\n\t" \
        "}" \
        :: "r"(d_tmem), "l"(a_desc), "l"(b_desc), "r"(idesc), "r"(_zero), "r"(_en) \
        : "memory"); \
} while(0)

// SW128 K-major smem descriptor (layout 2, version 1, LBO=1, SBO=64)
static constexpr uint64_t SMEM_DESC_BASE_SW128 =
    (uint64_t(2)  << 61) | (uint64_t(1) << 46) | (uint64_t(64) << 32) | (uint64_t(1) << 16);
#define MAKE_SMEM_DESC(base_addr) \
    (SMEM_DESC_BASE_SW128 | ((uint64_t)((base_addr) >> 4) & 0x3FFF))
#endif  // HAS_TCGEN05

#define SMEM_SWIZZLE_128B(byte_offset) \
    ((byte_offset) ^ (((byte_offset) >> 3) & 0x70))

__device__ __forceinline__ uint32_t smem_to_u32_gen(const void* p) {
    uint32_t a;
    asm("{ .reg .u64 t; cvta.to.shared.u64 t, %1; cvt.u32.u64 %0, t; }"
        : "=r"(a) : "l"(p));
    return a;
}

__device__ __forceinline__ float to_tf32(float x) {
    float y;
    asm("cvt.rna.tf32.f32 %0, %1;" : "=f"(y) : "f"(x));
    return y;
}

// ---------------------------------------------------------------------------
// GEMM: C[m,n] = sum_k A[m,k] * Bm[n,k] (+bias[n], or *scale with mask->-inf)
// sm_103a pass: tcgen05 split-tf32 (3xTF32), BM=BN=128, BK=32.
// other passes: SIMT fp32 (proven R1 path).
// ---------------------------------------------------------------------------
__global__ __launch_bounds__(256)
void mma_gemm_kernel(const float* __restrict__ A,
                     const float* __restrict__ Bm,
                     const float* __restrict__ bias,
                     const int*   __restrict__ mask,
                     float* __restrict__ C,
                     int N, int K,
                     long long strideA, long long strideB, long long strideC,
                     int maskStride, float scale)
{
    extern __shared__ __align__(1024) char smem[];

    const int tid = threadIdx.x;
    const int bz = blockIdx.z;
    A  += (size_t)bz * strideA;
    Bm += (size_t)bz * strideB;
    C  += (size_t)bz * strideC;
    if (mask) mask += (size_t)bz * maskStride;

    const int bm = blockIdx.y * 128;
    const int bn = blockIdx.x * 128;
    const float NEG_INF = __int_as_float(0xff800000u);

#if HAS_TCGEN05
    // ---------------- tcgen05 split-tf32 path ----------------
    constexpr int BK = 32;
    const uint32_t smem_base = smem_to_u32_gen(smem);
    const uint32_t mbar = smem_base + 0;
    const uint32_t tptr = smem_base + 8;
    int*   s_mask = (int*)(smem + 16);
    float* s_bias = (float*)(smem + 528);
    const int wid = tid >> 5;

    if (wid == 0) {
        TCGEN05_ALLOC(tptr, 128);
        TCGEN05_RELINQUISH();
    }
    if (tid == 0) MBARRIER_INIT(mbar, 1);
    if (tid < 128) {
        if (mask) s_mask[tid] = mask[bn + tid];
        if (bias) s_bias[tid] = bias[bn + tid];
    }
    __syncthreads();
    const uint32_t tmem = *(volatile uint32_t*)(smem + 8);

    constexpr uint32_t IDESC =
        (1u << 4)          // dtype = F32
        | (2u << 7)        // atype = TF32
        | (2u << 10)       // btype = TF32
        | ((128 / 8) << 17)
        | ((128 / 16) << 24);

    const uint64_t dAh = MAKE_SMEM_DESC(smem_base + SMEM_AH);
    const uint64_t dAl = MAKE_SMEM_DESC(smem_base + SMEM_AL);
    const uint64_t dBh = MAKE_SMEM_DESC(smem_base + SMEM_BH);
    const uint64_t dBl = MAKE_SMEM_DESC(smem_base + SMEM_BL);

    const int nch = K / BK;
    for (int c = 0; c < nch; c++) {
        const int k0 = c * BK;
        // Stage hi/lo tf32 tiles (128x32 each), SW128-swizzled.
#pragma unroll
        for (int t = 0; t < 4; t++) {
            int idx = tid + t * 256;          // 0..1023
            int row = idx >> 3;
            int c4  = idx & 7;
            uint32_t byte = (uint32_t)(row * 128 + c4 * 16);
            uint32_t sw = SMEM_SWIZZLE_128B(byte);

            float4 va = *(const float4*)(A + (size_t)(bm + row) * K + k0 + c4 * 4);
            float4 vh, vl;
            vh.x = to_tf32(va.x); vl.x = to_tf32(va.x - vh.x);
            vh.y = to_tf32(va.y); vl.y = to_tf32(va.y - vh.y);
            vh.z = to_tf32(va.z); vl.z = to_tf32(va.z - vh.z);
            vh.w = to_tf32(va.w); vl.w = to_tf32(va.w - vh.w);
            *(float4*)(smem + SMEM_AH + sw) = vh;
            *(float4*)(smem + SMEM_AL + sw) = vl;

            float4 vb = *(const float4*)(Bm + (size_t)(bn + row) * K + k0 + c4 * 4);
            vh.x = to_tf32(vb.x); vl.x = to_tf32(vb.x - vh.x);
            vh.y = to_tf32(vb.y); vl.y = to_tf32(vb.y - vh.y);
            vh.z = to_tf32(vb.z); vl.z = to_tf32(vb.z - vh.z);
            vh.w = to_tf32(vb.w); vl.w = to_tf32(vb.w - vh.w);
            *(float4*)(smem + SMEM_BH + sw) = vh;
            *(float4*)(smem + SMEM_BL + sw) = vl;
        }
        FENCE_PROXY_ASYNC_SHARED_CTA();
        __syncthreads();

        if (wid == 0 && elect_one_pred()) {
#pragma unroll
            for (int s = 0; s < 4; s++)
                TCGEN05_MMA_TF32_SS(tmem, dAh + s * 2, dBh + s * 2, IDESC,
                                    (c > 0) || (s > 0));
#pragma unroll
            for (int s = 0; s < 4; s++)
                TCGEN05_MMA_TF32_SS(tmem, dAh + s * 2, dBl + s * 2, IDESC, true);
#pragma unroll
            for (int s = 0; s < 4; s++)
                TCGEN05_MMA_TF32_SS(tmem, dAl + s * 2, dBh + s * 2, IDESC, true);
            TCGEN05_COMMIT(mbar);
        }
        MBARRIER_WAIT_PARITY(mbar, c & 1);
    }

    TCGEN05_FENCE_AFTER();

    if (wid < 4) {
        const int m = bm + wid * 32 + (tid & 31);
        float* crow = C + (size_t)m * N + bn;
#pragma unroll
        for (int i = 0; i < 4; i++) {
            uint32_t r[32];
            TCGEN05_LD_32X32B_X32(r, tmem + i * 32);
            TCGEN05_WAIT_LD();
            if (mask) {
#pragma unroll
                for (int j = 0; j < 32; j++) {
                    float v = __uint_as_float(r[j]) * scale;
                    if (s_mask[i * 32 + j] == 0) v = NEG_INF;
                    r[j] = __float_as_uint(v);
                }
            } else {
#pragma unroll
                for (int j = 0; j < 32; j++)
                    r[j] = __float_as_uint(__uint_as_float(r[j]) + s_bias[i * 32 + j]);
            }
#pragma unroll
            for (int j = 0; j < 8; j++)
                *(float4*)&crow[i * 32 + j * 4] = *(float4*)&r[j * 4];
        }
    }
    __syncthreads();
    if (wid == 0) TCGEN05_DEALLOC(tmem, 128);

#else
    // ---------------- SIMT fp32 fallback (proven) ----------------
    constexpr int BK = 16, TM = 8, TN = 8;
    float* As = (float*)smem;             // [BK][128]
    float* Bs = As + BK * 128;            // [BK][128]

    const int tx = tid & 15;
    const int ty = tid >> 4;

    float acc[TM][TN];
#pragma unroll
    for (int i = 0; i < TM; i++)
#pragma unroll
        for (int j = 0; j < TN; j++) acc[i][j] = 0.0f;

    for (int k0 = 0; k0 < K; k0 += BK) {
#pragma unroll
        for (int i = 0; i < 2; i++) {
            int li  = tid + i * 256;
            int row = li >> 2;
            int kc  = (li & 3) << 2;
            float4 va = *(const float4*)(A  + (size_t)(bm + row) * K + k0 + kc);
            As[(kc + 0) * 128 + row] = va.x; As[(kc + 1) * 128 + row] = va.y;
            As[(kc + 2) * 128 + row] = va.z; As[(kc + 3) * 128 + row] = va.w;
            float4 vb = *(const float4*)(Bm + (size_t)(bn + row) * K + k0 + kc);
            Bs[(kc + 0) * 128 + row] = vb.x; Bs[(kc + 1) * 128 + row] = vb.y;
            Bs[(kc + 2) * 128 + row] = vb.z; Bs[(kc + 3) * 128 + row] = vb.w;
        }
        __syncthreads();

#pragma unroll
        for (int kk = 0; kk < BK; kk++) {
            float a[TM], bb[TN];
            *(float4*)&a[0]  = *(const float4*)&As[kk * 128 + ty * TM];
            *(float4*)&a[4]  = *(const float4*)&As[kk * 128 + ty * TM + 4];
            *(float4*)&bb[0] = *(const float4*)&Bs[kk * 128 + tx * TN];
            *(float4*)&bb[4] = *(const float4*)&Bs[kk * 128 + tx * TN + 4];
#pragma unroll
            for (int i = 0; i < TM; i++)
#pragma unroll
                for (int j = 0; j < TN; j++)
                    acc[i][j] = fmaf(a[i], bb[j], acc[i][j]);
        }
        __syncthreads();
    }

    const int row0 = bm + ty * TM;
    const int col0 = bn + tx * TN;
    if (mask) {
        int mk[TN];
#pragma unroll
        for (int j = 0; j < TN; j++) mk[j] = mask[col0 + j];
#pragma unroll
        for (int i = 0; i < TM; i++) {
            float o[TN];
#pragma unroll
            for (int j = 0; j < TN; j++) {
                o[j] = acc[i][j] * scale;
                if (mk[j] == 0) o[j] = NEG_INF;
            }
            *(float4*)&C[(size_t)(row0 + i) * N + col0]     = make_float4(o[0], o[1], o[2], o[3]);
            *(float4*)&C[(size_t)(row0 + i) * N + col0 + 4] = make_float4(o[4], o[5], o[6], o[7]);
        }
    } else {
        float bb[TN];
#pragma unroll
        for (int j = 0; j < TN; j++) bb[j] = bias[col0 + j];
#pragma unroll
        for (int i = 0; i < TM; i++) {
            float o[TN];
#pragma unroll
            for (int j = 0; j < TN; j++) o[j] = acc[i][j] + bb[j];
            *(float4*)&C[(size_t)(row0 + i) * N + col0]     = make_float4(o[0], o[1], o[2], o[3]);
            *(float4*)&C[(size_t)(row0 + i) * N + col0 + 4] = make_float4(o[4], o[5], o[6], o[7]);
        }
    }
#endif
}

// ---------------------------------------------------------------------------
// Block reductions
// ---------------------------------------------------------------------------
__device__ __forceinline__ float block_reduce_max(float v)
{
    __shared__ float sm[8];
    for (int o = 16; o; o >>= 1) v = fmaxf(v, __shfl_xor_sync(0xffffffffu, v, o));
    if ((threadIdx.x & 31) == 0) sm[threadIdx.x >> 5] = v;
    __syncthreads();
    if (threadIdx.x < 32) {
        v = sm[threadIdx.x & 7];
        for (int o = 4; o; o >>= 1) v = fmaxf(v, __shfl_xor_sync(0xffffffffu, v, o));
        if (threadIdx.x == 0) sm[0] = v;
    }
    __syncthreads();
    float r = sm[0];
    __syncthreads();
    return r;
}

__device__ __forceinline__ float block_reduce_sum(float v)
{
    __shared__ float sm[8];
    for (int o = 16; o; o >>= 1) v += __shfl_xor_sync(0xffffffffu, v, o);
    if ((threadIdx.x & 31) == 0) sm[threadIdx.x >> 5] = v;
    __syncthreads();
    if (threadIdx.x < 32) {
        v = sm[threadIdx.x & 7];
        for (int o = 4; o; o >>= 1) v += __shfl_xor_sync(0xffffffffu, v, o);
        if (threadIdx.x == 0) sm[0] = v;
    }
    __syncthreads();
    float r = sm[0];
    __syncthreads();
    return r;
}

// ---------------------------------------------------------------------------
// Fused softmax + column-sum: never materializes probabilities.
// ---------------------------------------------------------------------------
__global__ __launch_bounds__(256)
void softmax_colsum_kernel(const float* __restrict__ P, float* __restrict__ wpart)
{
    const int ch = blockIdx.x;   // 0..QCH-1 (32 rows each)
    const int b  = blockIdx.y;
    const int tid = threadIdx.x;
    const float* base = P + ((size_t)b * kS + (size_t)ch * 32) * kS;

    float wacc[8];
#pragma unroll
    for (int i = 0; i < 8; i++) wacc[i] = 0.0f;

    for (int r = 0; r < 32; r++) {
        const float* p = base + (size_t)r * kS + tid * 8;
        float x[8];
        *(float4*)&x[0] = *(const float4*)&p[0];
        *(float4*)&x[4] = *(const float4*)&p[4];

        float m = x[0];
#pragma unroll
        for (int i = 1; i < 8; i++) m = fmaxf(m, x[i]);
        m = block_reduce_max(m);

        float e[8], s = 0.0f;
#pragma unroll
        for (int i = 0; i < 8; i++) {
            e[i] = __expf(x[i] - m);   // -inf -> 0 for masked keys
            s += e[i];
        }
        s = block_reduce_sum(s);
        const float inv = 1.0f / s;
#pragma unroll
        for (int i = 0; i < 8; i++) wacc[i] = fmaf(e[i], inv, wacc[i]);
    }

    float* o = wpart + (size_t)ch * (kB * kS) + (size_t)b * kS + tid * 8;
    *(float4*)&o[0] = make_float4(wacc[0], wacc[1], wacc[2], wacc[3]);
    *(float4*)&o[4] = make_float4(wacc[4], wacc[5], wacc[6], wacc[7]);
}

__global__ __launch_bounds__(256)
void colsum_reduce_kernel(const float* __restrict__ wpart, float* __restrict__ w)
{
    const int i = blockIdx.x * 256 + threadIdx.x;
    float s = 0.0f;
#pragma unroll
    for (int c = 0; c < QCH; c++) s += wpart[(size_t)c * (kB * kS) + i];
    w[i] = s;
}

// ---------------------------------------------------------------------------
// out[b,d] = (1/S) * sum_k w[b,k] * V[b,k,d]
// ---------------------------------------------------------------------------
__global__ __launch_bounds__(256)
void out_part_kernel(const float* __restrict__ w, const float* __restrict__ V,
                     float* __restrict__ opart)
{
    const int chunk = blockIdx.x;
    const int b     = blockIdx.y;
    const int d     = threadIdx.x;
    const float* vb = V + ((size_t)b * kS + (size_t)chunk * 64) * kD;
    const float* wb = w + b * kS + chunk * 64;
    float s = 0.0f;
#pragma unroll
    for (int k = 0; k < 64; k++) s = fmaf(wb[k], vb[(size_t)k * kD + d], s);
    opart[(size_t)(chunk * kB + b) * kD + d] = s;
}

__global__ __launch_bounds__(256)
void out_reduce_kernel(const float* __restrict__ opart, float* __restrict__ out)
{
    const int i = blockIdx.x * 256 + threadIdx.x;
    float s = 0.0f;
#pragma unroll
    for (int c = 0; c < N_KCHUNK; c++) s += opart[(size_t)c * (kB * kD) + i];
    out[i] = s * (1.0f / (float)kS);
}

// ---------------------------------------------------------------------------
// Launch
// ---------------------------------------------------------------------------
extern "C" void kernel_launch(void* const* d_in, const int* in_sizes, int n_in,
                              void* d_out, int out_size)
{
    const float* nodes = (const float*)d_in[0];
    const int*   mask  = (const int*)  d_in[1];
    const float* Wq    = (const float*)d_in[2];
    const float* bq    = (const float*)d_in[3];
    const float* Wk    = (const float*)d_in[4];
    const float* bk    = (const float*)d_in[5];
    const float* Wv    = (const float*)d_in[6];
    const float* bv    = (const float*)d_in[7];
    float* out = (float*)d_out;

    float *Q, *K, *V, *P, *w, *wpart, *opart;
    cudaGetSymbolAddress((void**)&Q,     g_Q);
    cudaGetSymbolAddress((void**)&K,     g_K);
    cudaGetSymbolAddress((void**)&V,     g_V);
    cudaGetSymbolAddress((void**)&P,     g_P);
    cudaGetSymbolAddress((void**)&w,     g_w);
    cudaGetSymbolAddress((void**)&wpart, g_wpart);
    cudaGetSymbolAddress((void**)&opart, g_opart);

    cudaFuncSetAttribute(mma_gemm_kernel,
                         cudaFuncAttributeMaxDynamicSharedMemorySize, SMEM_TOTAL);

    dim3 blk(256);

    // Projections: [16384,256] = nodes @ W^T + b
    dim3 gproj(kD / 128, kM / 128, 1);
    mma_gemm_kernel<<<gproj, blk, SMEM_TOTAL>>>(nodes, Wq, bq, nullptr, Q,
                                                kD, kD, 0, 0, 0, 0, 1.0f);
    mma_gemm_kernel<<<gproj, blk, SMEM_TOTAL>>>(nodes, Wk, bk, nullptr, K,
                                                kD, kD, 0, 0, 0, 0, 1.0f);
    mma_gemm_kernel<<<gproj, blk, SMEM_TOTAL>>>(nodes, Wv, bv, nullptr, V,
                                                kD, kD, 0, 0, 0, 0, 1.0f);

    // Scores: P[b] = Q[b] @ K[b]^T / 16, masked keys -> -inf
    dim3 gsc(kS / 128, kS / 128, kB);
    mma_gemm_kernel<<<gsc, blk, SMEM_TOTAL>>>(Q, K, nullptr, mask, P,
                                              kS, kD,
                                              (long long)kS * kD,
                                              (long long)kS * kD,
                                              (long long)kS * kS, kS, 0.0625f);

    // Fused softmax + column-sum partials (no prob materialization)
    softmax_colsum_kernel<<<dim3(QCH, kB), blk>>>(P, wpart);
    colsum_reduce_kernel<<<(kB * kS) / 256, blk>>>(wpart, w);

    // out[b,d] = (1/S) sum_k w[b,k] V[b,k,d]
    out_part_kernel<<<dim3(N_KCHUNK, kB), blk>>>(w, V, opart);
    out_reduce_kernel<<<(kB * kD) / 256, blk>>>(opart, out);
}